// round 5
// baseline (speedup 1.0000x reference)
#include <cuda_runtime.h>
#include <cstdint>
#include <math.h>

typedef unsigned long long ull;

__device__ __forceinline__ ull pack2(float lo, float hi) {
    ull r; asm("mov.b64 %0, {%1, %2};" : "=l"(r) : "f"(lo), "f"(hi)); return r;
}
__device__ __forceinline__ void unpack2(ull v, float& lo, float& hi) {
    asm("mov.b64 {%0, %1}, %2;" : "=f"(lo), "=f"(hi) : "l"(v));
}
__device__ __forceinline__ ull ffma2(ull a, ull b, ull c) {
    ull d; asm("fma.rn.f32x2 %0, %1, %2, %3;" : "=l"(d) : "l"(a), "l"(b), "l"(c)); return d;
}

static constexpr int B = 8, C = 128, T = 128, F = 512, K = 64;
static constexpr int FC = 128;     // F columns per CTA in main kernel
static constexpr int PXF = 128;    // pitch (floats) for 128-wide smem tiles
static constexpr int PXK = 68;     // pitch (floats) for 64-wide smem tiles (bank-skewed)

// scratch for k/v projections of the latent path: [b*T+t][c][k]
__device__ float g_kbuf[(size_t)B * T * C * K];
__device__ float g_vbuf[(size_t)B * T * C * K];

__device__ __forceinline__ float silu_f(float g) {
    float e = __expf(-g);
    return __fdividef(g, 1.0f + e);
}

// ===========================================================================
// 256-thread GEMM core for the latent kernel (unchanged from R4).
// ===========================================================================
template <int RT, int NP, int PX, int CH>
__device__ __forceinline__ void gemm_core(
    const float* __restrict__ Wglob,
    const float* __restrict__ Xin,
    ull* __restrict__ Wts,
    ull acc[RT][NP], int tid)
{
    const int tx = tid & 15, ty = tid >> 4;
    constexpr int R   = RT * 16;
    constexpr int PW2 = 2 * CH + 2;
    constexpr int C4  = CH / 4;
    constexpr int PT  = (R * C4) / 256;
    static_assert((R * C4) % 256 == 0, "staging divisibility");

    const int wbase = (ty >> 1) * PW2 + (ty & 1);

    float4 pf[PT];
    #pragma unroll
    for (int p = 0; p < PT; ++p) {
        int idx = tid + p * 256;
        int r = idx / C4, q = idx % C4;
        pf[p] = *reinterpret_cast<const float4*>(Wglob + r * 128 + q * 4);
    }

    for (int c0 = 0; c0 < 128; c0 += CH) {
        __syncthreads();
        #pragma unroll
        for (int p = 0; p < PT; ++p) {
            int idx = tid + p * 256;
            int r = idx / C4, q = idx % C4;
            ull* d = Wts + (r >> 1) * PW2 + (r & 1) + 2 * (q * 4);
            d[0] = pack2(pf[p].x, pf[p].x);
            d[2] = pack2(pf[p].y, pf[p].y);
            d[4] = pack2(pf[p].z, pf[p].z);
            d[6] = pack2(pf[p].w, pf[p].w);
        }
        __syncthreads();
        if (c0 + CH < 128) {
            #pragma unroll
            for (int p = 0; p < PT; ++p) {
                int idx = tid + p * 256;
                int r = idx / C4, q = idx % C4;
                pf[p] = *reinterpret_cast<const float4*>(Wglob + r * 128 + (c0 + CH) + q * 4);
            }
        }
        #pragma unroll 4
        for (int cc = 0; cc < CH; ++cc) {
            const float* xrow = Xin + (c0 + cc) * PX;
            ull xp[NP];
            #pragma unroll
            for (int jp = 0; jp < NP; ++jp)
                xp[jp] = *reinterpret_cast<const ull*>(xrow + 2 * (tx + 16 * jp));
            #pragma unroll
            for (int i = 0; i < RT; ++i) {
                ull wp = Wts[wbase + i * (8 * PW2) + 2 * cc];
                #pragma unroll
                for (int jp = 0; jp < NP; ++jp)
                    acc[i][jp] = ffma2(wp, xp[jp], acc[i][jp]);
            }
        }
    }
}

// ---------------------------------------------------------------------------
// Kernel 1: latent path (unchanged). One CTA per (b,t) frame, 2 CTAs/SM.
// ---------------------------------------------------------------------------
static constexpr int K1_XL = 0;
static constexpr int K1_LH = 128 * PXK;
static constexpr int K1_WT = K1_LH + 128 * PXK;
static constexpr int K1_WT_ULL = 64 * 34;
static constexpr int K1_RS = K1_WT + 2 * K1_WT_ULL;
static constexpr int K1_SMEM_BYTES = (K1_RS + 64) * 4;

__global__ void __launch_bounds__(256, 2) latent_kernel(
    const float* __restrict__ latent, const float* __restrict__ lp_gamma,
    const float* __restrict__ lp_w,   const float* __restrict__ lp_b,
    const float* __restrict__ k_w,    const float* __restrict__ k_b,
    const float* __restrict__ v_w,    const float* __restrict__ v_b)
{
    extern __shared__ float sm[];
    float* Xl  = sm + K1_XL;
    float* Lh  = sm + K1_LH;
    ull*   Wts = reinterpret_cast<ull*>(sm + K1_WT);
    float* rstd = sm + K1_RS;
    const int tid = threadIdx.x;
    const int frame = blockIdx.x;
    const int b = frame / T, t = frame % T;
    const int tx = tid & 15, ty = tid >> 4;

    const float* src = latent + ((size_t)b * C * T + t) * K;
    #pragma unroll
    for (int idx = tid; idx < 128 * 16; idx += 256) {
        int r = idx >> 4, q = idx & 15;
        float4 v = *reinterpret_cast<const float4*>(src + (size_t)r * (T * K) + q * 4);
        *reinterpret_cast<float4*>(Xl + r * PXK + q * 4) = v;
    }
    __syncthreads();
    if (tid < 64) {
        float s0 = 0, s1 = 0, s2 = 0, s3 = 0;
        for (int c = 0; c < 128; c += 4) {
            float a = Xl[c * PXK + tid], bb = Xl[(c + 1) * PXK + tid];
            float cc = Xl[(c + 2) * PXK + tid], dd = Xl[(c + 3) * PXK + tid];
            s0 += a * a; s1 += bb * bb; s2 += cc * cc; s3 += dd * dd;
        }
        rstd[tid] = rsqrtf((s0 + s1 + s2 + s3) * (1.0f / 128.0f) + 1e-6f);
    }
    __syncthreads();
    #pragma unroll
    for (int idx = tid; idx < 128 * 16; idx += 256) {
        int r = idx >> 4, q = idx & 15;
        float g = lp_gamma[r];
        float* d = Xl + r * PXK + q * 4;
        d[0] *= rstd[q * 4 + 0] * g; d[1] *= rstd[q * 4 + 1] * g;
        d[2] *= rstd[q * 4 + 2] * g; d[3] *= rstd[q * 4 + 3] * g;
    }

    {
        ull acc[8][2] = {};
        gemm_core<8, 2, PXK, 16>(lp_w, Xl, Wts, acc, tid);
        #pragma unroll
        for (int i = 0; i < 8; ++i) {
            int r = ty + 16 * i;
            float bias = lp_b[r];
            #pragma unroll
            for (int jp = 0; jp < 2; ++jp) {
                float lo, hi; unpack2(acc[i][jp], lo, hi);
                int fl = 2 * (tx + 16 * jp);
                Lh[r * PXK + fl]     = silu_f(lo + bias);
                Lh[r * PXK + fl + 1] = silu_f(hi + bias);
            }
        }
    }
    {
        ull acc[8][2] = {};
        gemm_core<8, 2, PXK, 16>(k_w, Lh, Wts, acc, tid);
        float* dst = g_kbuf + (size_t)frame * (C * K);
        #pragma unroll
        for (int i = 0; i < 8; ++i) {
            int r = ty + 16 * i;
            float bias = k_b[r];
            #pragma unroll
            for (int jp = 0; jp < 2; ++jp) {
                float lo, hi; unpack2(acc[i][jp], lo, hi);
                int fl = 2 * (tx + 16 * jp);
                *reinterpret_cast<float2*>(dst + r * K + fl) = make_float2(lo + bias, hi + bias);
            }
        }
    }
    {
        ull acc[8][2] = {};
        gemm_core<8, 2, PXK, 16>(v_w, Lh, Wts, acc, tid);
        float* dst = g_vbuf + (size_t)frame * (C * K);
        #pragma unroll
        for (int i = 0; i < 8; ++i) {
            int r = ty + 16 * i;
            float bias = v_b[r];
            #pragma unroll
            for (int jp = 0; jp < 2; ++jp) {
                float lo, hi; unpack2(acc[i][jp], lo, hi);
                int fl = 2 * (tx + 16 * jp);
                *reinterpret_cast<float2*>(dst + r * K + fl) = make_float2(lo + bias, hi + bias);
            }
        }
    }
}

// ===========================================================================
// 512-thread GEMM core for the main kernel.
// tx = tid&15 owns float-quads [4tx .. 4tx+3] and [4tx+64 .. 4tx+67].
// ty = tid>>4 (0..31) owns rows r = ty + 32*i, i<4. Warp = ty pair {2w,2w+1}.
// Weights staged per-parity: slot(r,cc) = (r&1)*(64*CH+4)
//    + (((r&31)>>1)*4 + (r>>5))*CH + cc   (ull idx; (w,w) duplicated pairs)
// -> inner-loop w fetch is ONE LDS.128 giving (w_cc, w_cc+1) for the row,
//    2 distinct addresses per warp (parity pair, +4 ull offset => different
//    bank quads) = 1 wavefront. X fetch = LDS.128 float4s.
// Per warp per cc: 4 LDS instr / 6 wavefronts / 16 FFMA2.
// acc[i][0..3]: [0]=floats(4tx,4tx+1) [1]=(4tx+2,4tx+3) [2..3]=same +64.
// ===========================================================================
static constexpr int CH5 = 16;
static constexpr int WPAR = 64 * CH5 + 4;    // parity-array stride in ull

__device__ __forceinline__ void gemm512(
    const float* __restrict__ Wglob,   // [128][128] row-major
    const float* __restrict__ Xin,     // smem tile, pitch PXF
    ull* __restrict__ Wts,             // 2*WPAR ull
    ull acc[4][4], int tid)
{
    const int tx = tid & 15, ty = tid >> 4;
    const int wbase = (ty & 1) * WPAR + (ty >> 1) * (4 * CH5);

    // staging map: 512 threads, 128 rows x 4 float4
    const int sr = tid >> 2, sq = tid & 3;
    const int wslot = (sr & 1) * WPAR + (((sr & 31) >> 1) * 4 + (sr >> 5)) * CH5 + sq * 4;

    float4 pf = *reinterpret_cast<const float4*>(Wglob + sr * 128 + sq * 4);

    for (int c0 = 0; c0 < 128; c0 += CH5) {
        __syncthreads();
        {
            ulonglong2 w01, w23;
            w01.x = pack2(pf.x, pf.x); w01.y = pack2(pf.y, pf.y);
            w23.x = pack2(pf.z, pf.z); w23.y = pack2(pf.w, pf.w);
            *reinterpret_cast<ulonglong2*>(Wts + wslot)     = w01;
            *reinterpret_cast<ulonglong2*>(Wts + wslot + 2) = w23;
        }
        __syncthreads();
        if (c0 + CH5 < 128)
            pf = *reinterpret_cast<const float4*>(Wglob + sr * 128 + (c0 + CH5) + sq * 4);

        #pragma unroll 2
        for (int cc2 = 0; cc2 < CH5; cc2 += 2) {
            ulonglong2 wv[4];
            #pragma unroll
            for (int i = 0; i < 4; ++i)
                wv[i] = *reinterpret_cast<const ulonglong2*>(Wts + wbase + i * CH5 + cc2);
            #pragma unroll
            for (int h = 0; h < 2; ++h) {
                const float* xrow = Xin + (c0 + cc2 + h) * PXF + 4 * tx;
                ulonglong2 x0 = *reinterpret_cast<const ulonglong2*>(xrow);
                ulonglong2 x1 = *reinterpret_cast<const ulonglong2*>(xrow + 64);
                #pragma unroll
                for (int i = 0; i < 4; ++i) {
                    ull w = h ? wv[i].y : wv[i].x;
                    acc[i][0] = ffma2(w, x0.x, acc[i][0]);
                    acc[i][1] = ffma2(w, x0.y, acc[i][1]);
                    acc[i][2] = ffma2(w, x1.x, acc[i][2]);
                    acc[i][3] = ffma2(w, x1.y, acc[i][3]);
                }
            }
        }
    }
}

// ---------------------------------------------------------------------------
// Kernel 2: fused side path + attention + FFN. 512 threads, 1 CTA/SM.
// ---------------------------------------------------------------------------
static constexpr int K2_XS = 0;
static constexpr int K2_HS = 128 * PXF;                 // 16384
static constexpr int K2_KS = K2_HS + 128 * PXF;         // 32768
static constexpr int K2_VS = K2_KS + 128 * PXK;         // 41472
static constexpr int K2_WT = K2_VS + 128 * PXK;         // 50176 (16B aligned)
static constexpr int K2_RS = K2_WT + 2 * (2 * WPAR);    // + 4112 floats
static constexpr int K2_SMEM_BYTES = (K2_RS + 128) * 4; // 217,664 B

__global__ void __launch_bounds__(512, 1) main_kernel(
    const float* __restrict__ side,      const float* __restrict__ basis,
    const float* __restrict__ qn_gamma,
    const float* __restrict__ qmlp_in_w, const float* __restrict__ qmlp_in_b,
    const float* __restrict__ qmlp_out_w,const float* __restrict__ qmlp_out_b,
    const float* __restrict__ q_w,       const float* __restrict__ q_b,
    const float* __restrict__ o_w,       const float* __restrict__ o_b,
    const float* __restrict__ ffn_gamma,
    const float* __restrict__ ffn_in_w,  const float* __restrict__ ffn_in_b,
    const float* __restrict__ ffn_out_w, const float* __restrict__ ffn_out_b,
    const float* __restrict__ score_scale, const float* __restrict__ prior_scale,
    const float* __restrict__ query_skip_scale,
    float* __restrict__ out)
{
    extern __shared__ float sm[];
    float* Xs  = sm + K2_XS;
    float* Hs  = sm + K2_HS;
    float* Ks  = sm + K2_KS;
    float* Vs  = sm + K2_VS;
    ull*   Wts = reinterpret_cast<ull*>(sm + K2_WT);
    float* rstd = sm + K2_RS;

    const int tid = threadIdx.x;
    const int fc = blockIdx.x;      // 0..3
    const int t  = blockIdx.y;
    const int b  = blockIdx.z;
    const int f0 = fc * FC;
    const int tx = tid & 15, ty = tid >> 4;   // ty 0..31
    const int frame = b * T + t;

    // ---- load k/v frame into smem (pitch 64 -> 68) ----
    {
        const float* ksrc = g_kbuf + (size_t)frame * (C * K);
        const float* vsrc = g_vbuf + (size_t)frame * (C * K);
        #pragma unroll
        for (int idx = tid; idx < 128 * 16; idx += 512) {
            int r = idx >> 4, q = idx & 15;
            float4 kv = *reinterpret_cast<const float4*>(ksrc + r * K + q * 4);
            float4 vv = *reinterpret_cast<const float4*>(vsrc + r * K + q * 4);
            *reinterpret_cast<float4*>(Ks + r * PXK + q * 4) = kv;
            *reinterpret_cast<float4*>(Vs + r * PXK + q * 4) = vv;
        }
    }
    // ---- load side chunk [128][128] ----
    const float* sbase = side + ((size_t)b * C * T + t) * F + f0;
    #pragma unroll
    for (int idx = tid; idx < 128 * 32; idx += 512) {
        int r = idx >> 5, q = idx & 31;
        float4 v = *reinterpret_cast<const float4*>(sbase + (size_t)r * (T * F) + q * 4);
        *reinterpret_cast<float4*>(Xs + r * PXF + q * 4) = v;
    }
    __syncthreads();
    // ---- rmsnorm (axis C) ----
    if (tid < 128) {
        float s0 = 0, s1 = 0, s2 = 0, s3 = 0;
        for (int c = 0; c < 128; c += 4) {
            float a = Xs[c * PXF + tid], bb = Xs[(c + 1) * PXF + tid];
            float cc = Xs[(c + 2) * PXF + tid], dd = Xs[(c + 3) * PXF + tid];
            s0 += a * a; s1 += bb * bb; s2 += cc * cc; s3 += dd * dd;
        }
        rstd[tid] = rsqrtf((s0 + s1 + s2 + s3) * (1.0f / 128.0f) + 1e-6f);
    }
    __syncthreads();
    #pragma unroll
    for (int idx = tid; idx < 128 * 32; idx += 512) {
        int r = idx >> 5, q = idx & 31;
        float g = qn_gamma[r];
        float* d = Xs + r * PXF + q * 4;
        d[0] *= rstd[q * 4 + 0] * g; d[1] *= rstd[q * 4 + 1] * g;
        d[2] *= rstd[q * 4 + 2] * g; d[3] *= rstd[q * 4 + 3] * g;
    }

    // epilogue helper lambdas -------------------------------------------------
    auto acc_to_f4 = [](ull a0, ull a1, float bias) {
        float4 v;
        unpack2(a0, v.x, v.y); unpack2(a1, v.z, v.w);
        v.x += bias; v.y += bias; v.z += bias; v.w += bias;
        return v;
    };

    // ---- GEMM1: qmlp_in (gated, two 128-row passes) -> m in Hs ----
    {   // pass 1: gate rows -> silu(g) into Hs
        ull acc[4][4] = {};
        gemm512(qmlp_in_w + 128 * 128, Xs, Wts, acc, tid);
        #pragma unroll
        for (int i = 0; i < 4; ++i) {
            int r = ty + 32 * i;
            float bg = qmlp_in_b[r + 128];
            float4 va = acc_to_f4(acc[i][0], acc[i][1], bg);
            float4 vb = acc_to_f4(acc[i][2], acc[i][3], bg);
            va.x = silu_f(va.x); va.y = silu_f(va.y); va.z = silu_f(va.z); va.w = silu_f(va.w);
            vb.x = silu_f(vb.x); vb.y = silu_f(vb.y); vb.z = silu_f(vb.z); vb.w = silu_f(vb.w);
            *reinterpret_cast<float4*>(Hs + r * PXF + 4 * tx)      = va;
            *reinterpret_cast<float4*>(Hs + r * PXF + 4 * tx + 64) = vb;
        }
    }
    {   // pass 2: a rows; m = (a+b) * silu(g)
        ull acc[4][4] = {};
        gemm512(qmlp_in_w, Xs, Wts, acc, tid);
        #pragma unroll
        for (int i = 0; i < 4; ++i) {
            int r = ty + 32 * i;
            float ba = qmlp_in_b[r];
            float4 va = acc_to_f4(acc[i][0], acc[i][1], ba);
            float4 vb = acc_to_f4(acc[i][2], acc[i][3], ba);
            float4 g0 = *reinterpret_cast<float4*>(Hs + r * PXF + 4 * tx);
            float4 g1 = *reinterpret_cast<float4*>(Hs + r * PXF + 4 * tx + 64);
            g0.x *= va.x; g0.y *= va.y; g0.z *= va.z; g0.w *= va.w;
            g1.x *= vb.x; g1.y *= vb.y; g1.z *= vb.z; g1.w *= vb.w;
            *reinterpret_cast<float4*>(Hs + r * PXF + 4 * tx)      = g0;
            *reinterpret_cast<float4*>(Hs + r * PXF + 4 * tx + 64) = g1;
        }
    }
    // ---- GEMM2: qmlp_out -> query_h in Xs ----
    {
        ull acc[4][4] = {};
        gemm512(qmlp_out_w, Hs, Wts, acc, tid);
        #pragma unroll
        for (int i = 0; i < 4; ++i) {
            int r = ty + 32 * i;
            float bias = qmlp_out_b[r];
            *reinterpret_cast<float4*>(Xs + r * PXF + 4 * tx)      = acc_to_f4(acc[i][0], acc[i][1], bias);
            *reinterpret_cast<float4*>(Xs + r * PXF + 4 * tx + 64) = acc_to_f4(acc[i][2], acc[i][3], bias);
        }
    }
    // ---- GEMM3: q projection -> Hs ----
    {
        ull acc[4][4] = {};
        gemm512(q_w, Xs, Wts, acc, tid);
        #pragma unroll
        for (int i = 0; i < 4; ++i) {
            int r = ty + 32 * i;
            float bias = q_b[r];
            *reinterpret_cast<float4*>(Hs + r * PXF + 4 * tx)      = acc_to_f4(acc[i][0], acc[i][1], bias);
            *reinterpret_cast<float4*>(Hs + r * PXF + 4 * tx + 64) = acc_to_f4(acc[i][2], acc[i][3], bias);
        }
    }
    __syncthreads();   // q fully in Hs before scores

    // ---- scores [f][k] + softmax over k. 512 threads: 2 f x 8 k each ----
    const int kg = tid & 7, fg = tid >> 3;    // fg 0..63
    float wgt[2][8];
    {
        ull sacc[2][4] = {};
        #pragma unroll 4
        for (int c = 0; c < 128; ++c) {
            float2 qv = *reinterpret_cast<const float2*>(Hs + c * PXF + 2 * fg);
            const ulonglong2* kr = reinterpret_cast<const ulonglong2*>(Ks + c * PXK + kg * 8);
            ulonglong2 k0 = kr[0], k1 = kr[1];
            ull qp0 = pack2(qv.x, qv.x), qp1 = pack2(qv.y, qv.y);
            sacc[0][0] = ffma2(qp0, k0.x, sacc[0][0]);
            sacc[0][1] = ffma2(qp0, k0.y, sacc[0][1]);
            sacc[0][2] = ffma2(qp0, k1.x, sacc[0][2]);
            sacc[0][3] = ffma2(qp0, k1.y, sacc[0][3]);
            sacc[1][0] = ffma2(qp1, k0.x, sacc[1][0]);
            sacc[1][1] = ffma2(qp1, k0.y, sacc[1][1]);
            sacc[1][2] = ffma2(qp1, k1.x, sacc[1][2]);
            sacc[1][3] = ffma2(qp1, k1.y, sacc[1][3]);
        }
        const float ssc = *score_scale, psc = *prior_scale;
        #pragma unroll
        for (int i = 0; i < 2; ++i) {
            float s[8];
            #pragma unroll
            for (int jp = 0; jp < 4; ++jp) unpack2(sacc[i][jp], s[2 * jp], s[2 * jp + 1]);
            int fglob = f0 + 2 * fg + i;
            #pragma unroll
            for (int j = 0; j < 8; ++j)
                s[j] = s[j] * ssc + basis[(kg * 8 + j) * F + fglob] * psc;
            float m = s[0];
            #pragma unroll
            for (int j = 1; j < 8; ++j) m = fmaxf(m, s[j]);
            #pragma unroll
            for (int d = 1; d < 8; d <<= 1) m = fmaxf(m, __shfl_xor_sync(0xffffffffu, m, d));
            float sum = 0;
            #pragma unroll
            for (int j = 0; j < 8; ++j) { float e = __expf(s[j] - m); wgt[i][j] = e; sum += e; }
            #pragma unroll
            for (int d = 1; d < 8; d <<= 1) sum += __shfl_xor_sync(0xffffffffu, sum, d);
            float inv = __frcp_rn(sum);
            #pragma unroll
            for (int j = 0; j < 8; ++j) wgt[i][j] *= inv;
        }
    }
    __syncthreads();   // all reads of Ks + q reads of Hs done
    {   // store weights transposed into the dead Ks region: Ws[k][f], pitch PXF
        float* Ws = Ks;
        #pragma unroll
        for (int j = 0; j < 8; ++j)
            *reinterpret_cast<float2*>(Ws + (kg * 8 + j) * PXF + 2 * fg) =
                make_float2(wgt[0][j], wgt[1][j]);
    }
    __syncthreads();
    // ---- attended[c][f] = sum_k Ws[k][f] * Vs[c][k] -> Hs ----
    {
        ull acc[4][4] = {};
        const float* Ws = Ks;
        #pragma unroll 4
        for (int kk = 0; kk < 64; ++kk) {
            const float* wsrow = Ws + kk * PXF + 4 * tx;
            ulonglong2 x0 = *reinterpret_cast<const ulonglong2*>(wsrow);
            ulonglong2 x1 = *reinterpret_cast<const ulonglong2*>(wsrow + 64);
            #pragma unroll
            for (int i = 0; i < 4; ++i) {
                float v = Vs[(ty + 32 * i) * PXK + kk];
                ull vp = pack2(v, v);
                acc[i][0] = ffma2(vp, x0.x, acc[i][0]);
                acc[i][1] = ffma2(vp, x0.y, acc[i][1]);
                acc[i][2] = ffma2(vp, x1.x, acc[i][2]);
                acc[i][3] = ffma2(vp, x1.y, acc[i][3]);
            }
        }
        #pragma unroll
        for (int i = 0; i < 4; ++i) {
            int r = ty + 32 * i;
            *reinterpret_cast<float4*>(Hs + r * PXF + 4 * tx)      = acc_to_f4(acc[i][0], acc[i][1], 0.0f);
            *reinterpret_cast<float4*>(Hs + r * PXF + 4 * tx + 64) = acc_to_f4(acc[i][2], acc[i][3], 0.0f);
        }
    }
    // ---- GEMM4: hidden = o_w @ attended + o_b + qss*query_h -> Xs (in place) ----
    {
        ull acc[4][4] = {};
        gemm512(o_w, Hs, Wts, acc, tid);
        const float qs = *query_skip_scale;
        #pragma unroll
        for (int i = 0; i < 4; ++i) {
            int r = ty + 32 * i;
            float bias = o_b[r];
            float4 va = acc_to_f4(acc[i][0], acc[i][1], bias);
            float4 vb = acc_to_f4(acc[i][2], acc[i][3], bias);
            float4 qa = *reinterpret_cast<float4*>(Xs + r * PXF + 4 * tx);
            float4 qb = *reinterpret_cast<float4*>(Xs + r * PXF + 4 * tx + 64);
            va.x += qs * qa.x; va.y += qs * qa.y; va.z += qs * qa.z; va.w += qs * qa.w;
            vb.x += qs * qb.x; vb.y += qs * qb.y; vb.z += qs * qb.z; vb.w += qs * qb.w;
            *reinterpret_cast<float4*>(Xs + r * PXF + 4 * tx)      = va;
            *reinterpret_cast<float4*>(Xs + r * PXF + 4 * tx + 64) = vb;
        }
    }
    __syncthreads();
    // ---- FFN rmsnorm: Hs = rmsnorm(Xs)*ffn_gamma ----
    if (tid < 128) {
        float s0 = 0, s1 = 0, s2 = 0, s3 = 0;
        for (int c = 0; c < 128; c += 4) {
            float a = Xs[c * PXF + tid], bb = Xs[(c + 1) * PXF + tid];
            float cc = Xs[(c + 2) * PXF + tid], dd = Xs[(c + 3) * PXF + tid];
            s0 += a * a; s1 += bb * bb; s2 += cc * cc; s3 += dd * dd;
        }
        rstd[tid] = rsqrtf((s0 + s1 + s2 + s3) * (1.0f / 128.0f) + 1e-6f);
    }
    __syncthreads();
    #pragma unroll
    for (int idx = tid; idx < 128 * 32; idx += 512) {
        int r = idx >> 5, q = idx & 31;
        float g = ffn_gamma[r];
        const float* s = Xs + r * PXF + q * 4;
        float* d = Hs + r * PXF + q * 4;
        d[0] = s[0] * rstd[q * 4 + 0] * g; d[1] = s[1] * rstd[q * 4 + 1] * g;
        d[2] = s[2] * rstd[q * 4 + 2] * g; d[3] = s[3] * rstd[q * 4 + 3] * g;
    }
    // ---- GEMM5: ffn_in (gated, two passes), intermediate Gb = dead Ks+Vs ----
    float* Gb = Ks;
    {   // pass 1: gate rows -> silu into Gb
        ull acc[4][4] = {};
        gemm512(ffn_in_w + 128 * 128, Hs, Wts, acc, tid);
        #pragma unroll
        for (int i = 0; i < 4; ++i) {
            int r = ty + 32 * i;
            float bg = ffn_in_b[r + 128];
            float4 va = acc_to_f4(acc[i][0], acc[i][1], bg);
            float4 vb = acc_to_f4(acc[i][2], acc[i][3], bg);
            va.x = silu_f(va.x); va.y = silu_f(va.y); va.z = silu_f(va.z); va.w = silu_f(va.w);
            vb.x = silu_f(vb.x); vb.y = silu_f(vb.y); vb.z = silu_f(vb.z); vb.w = silu_f(vb.w);
            *reinterpret_cast<float4*>(Gb + r * PXF + 4 * tx)      = va;
            *reinterpret_cast<float4*>(Gb + r * PXF + 4 * tx + 64) = vb;
        }
    }
    {   // pass 2: a rows; m2 = (a+b)*silu(g) into Gb
        ull acc[4][4] = {};
        gemm512(ffn_in_w, Hs, Wts, acc, tid);
        #pragma unroll
        for (int i = 0; i < 4; ++i) {
            int r = ty + 32 * i;
            float ba = ffn_in_b[r];
            float4 va = acc_to_f4(acc[i][0], acc[i][1], ba);
            float4 vb = acc_to_f4(acc[i][2], acc[i][3], ba);
            float4 g0 = *reinterpret_cast<float4*>(Gb + r * PXF + 4 * tx);
            float4 g1 = *reinterpret_cast<float4*>(Gb + r * PXF + 4 * tx + 64);
            g0.x *= va.x; g0.y *= va.y; g0.z *= va.z; g0.w *= va.w;
            g1.x *= vb.x; g1.y *= vb.y; g1.z *= vb.z; g1.w *= vb.w;
            *reinterpret_cast<float4*>(Gb + r * PXF + 4 * tx)      = g0;
            *reinterpret_cast<float4*>(Gb + r * PXF + 4 * tx + 64) = g1;
        }
    }
    // ---- GEMM6: out = ffn_out @ m2 + ffn_out_b + hidden -> global ----
    {
        ull acc[4][4] = {};
        gemm512(ffn_out_w, Gb, Wts, acc, tid);
        float* obase = out + ((size_t)b * C * T + t) * F + f0;
        #pragma unroll
        for (int i = 0; i < 4; ++i) {
            int r = ty + 32 * i;
            float bias = ffn_out_b[r];
            float4 va = acc_to_f4(acc[i][0], acc[i][1], bias);
            float4 vb = acc_to_f4(acc[i][2], acc[i][3], bias);
            float4 ha = *reinterpret_cast<float4*>(Xs + r * PXF + 4 * tx);
            float4 hb = *reinterpret_cast<float4*>(Xs + r * PXF + 4 * tx + 64);
            va.x += ha.x; va.y += ha.y; va.z += ha.z; va.w += ha.w;
            vb.x += hb.x; vb.y += hb.y; vb.z += hb.z; vb.w += hb.w;
            *reinterpret_cast<float4*>(obase + (size_t)r * (T * F) + 4 * tx)      = va;
            *reinterpret_cast<float4*>(obase + (size_t)r * (T * F) + 4 * tx + 64) = vb;
        }
    }
}

// ---------------------------------------------------------------------------
extern "C" void kernel_launch(void* const* d_in, const int* in_sizes, int n_in,
                              void* d_out, int out_size)
{
    const float* latent      = (const float*)d_in[0];
    const float* side        = (const float*)d_in[1];
    const float* basis       = (const float*)d_in[2];
    const float* lp_gamma    = (const float*)d_in[3];
    const float* lp_w        = (const float*)d_in[4];
    const float* lp_b        = (const float*)d_in[5];
    const float* qn_gamma    = (const float*)d_in[6];
    const float* qmlp_in_w   = (const float*)d_in[7];
    const float* qmlp_in_b   = (const float*)d_in[8];
    const float* qmlp_out_w  = (const float*)d_in[9];
    const float* qmlp_out_b  = (const float*)d_in[10];
    const float* q_w         = (const float*)d_in[11];
    const float* q_b         = (const float*)d_in[12];
    const float* k_w         = (const float*)d_in[13];
    const float* k_b         = (const float*)d_in[14];
    const float* v_w         = (const float*)d_in[15];
    const float* v_b         = (const float*)d_in[16];
    const float* o_w         = (const float*)d_in[17];
    const float* o_b         = (const float*)d_in[18];
    const float* ffn_gamma   = (const float*)d_in[19];
    const float* ffn_in_w    = (const float*)d_in[20];
    const float* ffn_in_b    = (const float*)d_in[21];
    const float* ffn_out_w   = (const float*)d_in[22];
    const float* ffn_out_b   = (const float*)d_in[23];
    const float* score_scale = (const float*)d_in[24];
    const float* prior_scale = (const float*)d_in[25];
    const float* qss         = (const float*)d_in[26];
    float* out = (float*)d_out;

    cudaFuncSetAttribute(latent_kernel, cudaFuncAttributeMaxDynamicSharedMemorySize, K1_SMEM_BYTES);
    cudaFuncSetAttribute(main_kernel,   cudaFuncAttributeMaxDynamicSharedMemorySize, K2_SMEM_BYTES);

    latent_kernel<<<B * T, 256, K1_SMEM_BYTES>>>(
        latent, lp_gamma, lp_w, lp_b, k_w, k_b, v_w, v_b);

    main_kernel<<<dim3(F / FC, T, B), 512, K2_SMEM_BYTES>>>(
        side, basis, qn_gamma,
        qmlp_in_w, qmlp_in_b, qmlp_out_w, qmlp_out_b,
        q_w, q_b, o_w, o_b,
        ffn_gamma, ffn_in_w, ffn_in_b, ffn_out_w, ffn_out_b,
        score_scale, prior_scale, qss, out);
}

// round 7
// speedup vs baseline: 1.0008x; 1.0008x over previous
#include <cuda_runtime.h>
#include <cstdint>
#include <math.h>

typedef unsigned long long ull;

__device__ __forceinline__ ull pack2(float lo, float hi) {
    ull r; asm("mov.b64 %0, {%1, %2};" : "=l"(r) : "f"(lo), "f"(hi)); return r;
}
__device__ __forceinline__ void unpack2(ull v, float& lo, float& hi) {
    asm("mov.b64 {%0, %1}, %2;" : "=f"(lo), "=f"(hi) : "l"(v));
}
__device__ __forceinline__ ull ffma2(ull a, ull b, ull c) {
    ull d; asm("fma.rn.f32x2 %0, %1, %2, %3;" : "=l"(d) : "l"(a), "l"(b), "l"(c)); return d;
}

static constexpr int B = 8, C = 128, T = 128, F = 512, K = 64;
static constexpr int FC = 128;     // F columns per CTA in main kernel
static constexpr int PXF = 128;    // pitch (floats) for 128-wide smem tiles
static constexpr int PXK = 68;     // pitch (floats) for 64-wide smem tiles (bank-skewed)

// scratch for k/v projections of the latent path: [b*T+t][c][k]
__device__ float g_kbuf[(size_t)B * T * C * K];
__device__ float g_vbuf[(size_t)B * T * C * K];

__device__ __forceinline__ float silu_f(float g) {
    float e = __expf(-g);
    return __fdividef(g, 1.0f + e);
}

// ===========================================================================
// 256-thread GEMM core for the latent kernel (unchanged from R4).
// ===========================================================================
template <int RT, int NP, int PX, int CH>
__device__ __forceinline__ void gemm_core(
    const float* __restrict__ Wglob,
    const float* __restrict__ Xin,
    ull* __restrict__ Wts,
    ull acc[RT][NP], int tid)
{
    const int tx = tid & 15, ty = tid >> 4;
    constexpr int R   = RT * 16;
    constexpr int PW2 = 2 * CH + 2;
    constexpr int C4  = CH / 4;
    constexpr int PT  = (R * C4) / 256;
    static_assert((R * C4) % 256 == 0, "staging divisibility");

    const int wbase = (ty >> 1) * PW2 + (ty & 1);

    float4 pf[PT];
    #pragma unroll
    for (int p = 0; p < PT; ++p) {
        int idx = tid + p * 256;
        int r = idx / C4, q = idx % C4;
        pf[p] = *reinterpret_cast<const float4*>(Wglob + r * 128 + q * 4);
    }

    for (int c0 = 0; c0 < 128; c0 += CH) {
        __syncthreads();
        #pragma unroll
        for (int p = 0; p < PT; ++p) {
            int idx = tid + p * 256;
            int r = idx / C4, q = idx % C4;
            ull* d = Wts + (r >> 1) * PW2 + (r & 1) + 2 * (q * 4);
            d[0] = pack2(pf[p].x, pf[p].x);
            d[2] = pack2(pf[p].y, pf[p].y);
            d[4] = pack2(pf[p].z, pf[p].z);
            d[6] = pack2(pf[p].w, pf[p].w);
        }
        __syncthreads();
        if (c0 + CH < 128) {
            #pragma unroll
            for (int p = 0; p < PT; ++p) {
                int idx = tid + p * 256;
                int r = idx / C4, q = idx % C4;
                pf[p] = *reinterpret_cast<const float4*>(Wglob + r * 128 + (c0 + CH) + q * 4);
            }
        }
        #pragma unroll 4
        for (int cc = 0; cc < CH; ++cc) {
            const float* xrow = Xin + (c0 + cc) * PX;
            ull xp[NP];
            #pragma unroll
            for (int jp = 0; jp < NP; ++jp)
                xp[jp] = *reinterpret_cast<const ull*>(xrow + 2 * (tx + 16 * jp));
            #pragma unroll
            for (int i = 0; i < RT; ++i) {
                ull wp = Wts[wbase + i * (8 * PW2) + 2 * cc];
                #pragma unroll
                for (int jp = 0; jp < NP; ++jp)
                    acc[i][jp] = ffma2(wp, xp[jp], acc[i][jp]);
            }
        }
    }
}

// ---------------------------------------------------------------------------
// Kernel 1: latent path (unchanged). One CTA per (b,t) frame, 2 CTAs/SM.
// ---------------------------------------------------------------------------
static constexpr int K1_XL = 0;
static constexpr int K1_LH = 128 * PXK;
static constexpr int K1_WT = K1_LH + 128 * PXK;
static constexpr int K1_WT_ULL = 64 * 34;
static constexpr int K1_RS = K1_WT + 2 * K1_WT_ULL;
static constexpr int K1_SMEM_BYTES = (K1_RS + 64) * 4;

__global__ void __launch_bounds__(256, 2) latent_kernel(
    const float* __restrict__ latent, const float* __restrict__ lp_gamma,
    const float* __restrict__ lp_w,   const float* __restrict__ lp_b,
    const float* __restrict__ k_w,    const float* __restrict__ k_b,
    const float* __restrict__ v_w,    const float* __restrict__ v_b)
{
    extern __shared__ float sm[];
    float* Xl  = sm + K1_XL;
    float* Lh  = sm + K1_LH;
    ull*   Wts = reinterpret_cast<ull*>(sm + K1_WT);
    float* rstd = sm + K1_RS;
    const int tid = threadIdx.x;
    const int frame = blockIdx.x;
    const int b = frame / T, t = frame % T;
    const int tx = tid & 15, ty = tid >> 4;

    const float* src = latent + ((size_t)b * C * T + t) * K;
    #pragma unroll
    for (int idx = tid; idx < 128 * 16; idx += 256) {
        int r = idx >> 4, q = idx & 15;
        float4 v = *reinterpret_cast<const float4*>(src + (size_t)r * (T * K) + q * 4);
        *reinterpret_cast<float4*>(Xl + r * PXK + q * 4) = v;
    }
    __syncthreads();
    if (tid < 64) {
        float s0 = 0, s1 = 0, s2 = 0, s3 = 0;
        for (int c = 0; c < 128; c += 4) {
            float a = Xl[c * PXK + tid], bb = Xl[(c + 1) * PXK + tid];
            float cc = Xl[(c + 2) * PXK + tid], dd = Xl[(c + 3) * PXK + tid];
            s0 += a * a; s1 += bb * bb; s2 += cc * cc; s3 += dd * dd;
        }
        rstd[tid] = rsqrtf((s0 + s1 + s2 + s3) * (1.0f / 128.0f) + 1e-6f);
    }
    __syncthreads();
    #pragma unroll
    for (int idx = tid; idx < 128 * 16; idx += 256) {
        int r = idx >> 4, q = idx & 15;
        float g = lp_gamma[r];
        float* d = Xl + r * PXK + q * 4;
        d[0] *= rstd[q * 4 + 0] * g; d[1] *= rstd[q * 4 + 1] * g;
        d[2] *= rstd[q * 4 + 2] * g; d[3] *= rstd[q * 4 + 3] * g;
    }

    {
        ull acc[8][2] = {};
        gemm_core<8, 2, PXK, 16>(lp_w, Xl, Wts, acc, tid);
        #pragma unroll
        for (int i = 0; i < 8; ++i) {
            int r = ty + 16 * i;
            float bias = lp_b[r];
            #pragma unroll
            for (int jp = 0; jp < 2; ++jp) {
                float lo, hi; unpack2(acc[i][jp], lo, hi);
                int fl = 2 * (tx + 16 * jp);
                Lh[r * PXK + fl]     = silu_f(lo + bias);
                Lh[r * PXK + fl + 1] = silu_f(hi + bias);
            }
        }
    }
    {
        ull acc[8][2] = {};
        gemm_core<8, 2, PXK, 16>(k_w, Lh, Wts, acc, tid);
        float* dst = g_kbuf + (size_t)frame * (C * K);
        #pragma unroll
        for (int i = 0; i < 8; ++i) {
            int r = ty + 16 * i;
            float bias = k_b[r];
            #pragma unroll
            for (int jp = 0; jp < 2; ++jp) {
                float lo, hi; unpack2(acc[i][jp], lo, hi);
                int fl = 2 * (tx + 16 * jp);
                *reinterpret_cast<float2*>(dst + r * K + fl) = make_float2(lo + bias, hi + bias);
            }
        }
    }
    {
        ull acc[8][2] = {};
        gemm_core<8, 2, PXK, 16>(v_w, Lh, Wts, acc, tid);
        float* dst = g_vbuf + (size_t)frame * (C * K);
        #pragma unroll
        for (int i = 0; i < 8; ++i) {
            int r = ty + 16 * i;
            float bias = v_b[r];
            #pragma unroll
            for (int jp = 0; jp < 2; ++jp) {
                float lo, hi; unpack2(acc[i][jp], lo, hi);
                int fl = 2 * (tx + 16 * jp);
                *reinterpret_cast<float2*>(dst + r * K + fl) = make_float2(lo + bias, hi + bias);
            }
        }
    }
}

// ===========================================================================
// 512-thread GEMM core for the main kernel.
// tx = tid&15 owns float-quads [4tx .. 4tx+3] and [4tx+64 .. 4tx+67].
// ty = tid>>4 (0..31) owns rows r = ty + 32*i, i<4. Warp = ty pair {2w,2w+1}.
// Weights staged per-parity as duplicated (w,w) pairs; inner-loop w fetch is
// ONE LDS.128 giving (w_cc, w_cc+1), 2 distinct addrs/warp (different bank
// quads via +4-ull parity offset) = 1 wavefront. X fetch = LDS.128 float4s.
// Per warp per cc: 4 LDS instr / 6 wavefronts / 16 FFMA2.
// ===========================================================================
static constexpr int CH5 = 16;
static constexpr int WPAR = 64 * CH5 + 4;    // parity-array stride in ull

__device__ __forceinline__ void gemm512(
    const float* __restrict__ Wglob,   // [128][128] row-major
    const float* __restrict__ Xin,     // smem tile, pitch PXF
    ull* __restrict__ Wts,             // 2*WPAR ull
    ull acc[4][4], int tid)
{
    const int tx = tid & 15, ty = tid >> 4;
    const int wbase = (ty & 1) * WPAR + (ty >> 1) * (4 * CH5);

    // staging map: 512 threads, 128 rows x 4 float4
    const int sr = tid >> 2, sq = tid & 3;
    const int wslot = (sr & 1) * WPAR + (((sr & 31) >> 1) * 4 + (sr >> 5)) * CH5 + sq * 4;

    float4 pf = *reinterpret_cast<const float4*>(Wglob + sr * 128 + sq * 4);

    for (int c0 = 0; c0 < 128; c0 += CH5) {
        __syncthreads();
        {
            ulonglong2 w01, w23;
            w01.x = pack2(pf.x, pf.x); w01.y = pack2(pf.y, pf.y);
            w23.x = pack2(pf.z, pf.z); w23.y = pack2(pf.w, pf.w);
            *reinterpret_cast<ulonglong2*>(Wts + wslot)     = w01;
            *reinterpret_cast<ulonglong2*>(Wts + wslot + 2) = w23;
        }
        __syncthreads();
        if (c0 + CH5 < 128)
            pf = *reinterpret_cast<const float4*>(Wglob + sr * 128 + (c0 + CH5) + sq * 4);

        #pragma unroll 2
        for (int cc2 = 0; cc2 < CH5; cc2 += 2) {
            ulonglong2 wv[4];
            #pragma unroll
            for (int i = 0; i < 4; ++i)
                wv[i] = *reinterpret_cast<const ulonglong2*>(Wts + wbase + i * CH5 + cc2);
            #pragma unroll
            for (int h = 0; h < 2; ++h) {
                const float* xrow = Xin + (c0 + cc2 + h) * PXF + 4 * tx;
                ulonglong2 x0 = *reinterpret_cast<const ulonglong2*>(xrow);
                ulonglong2 x1 = *reinterpret_cast<const ulonglong2*>(xrow + 64);
                #pragma unroll
                for (int i = 0; i < 4; ++i) {
                    ull w = h ? wv[i].y : wv[i].x;
                    acc[i][0] = ffma2(w, x0.x, acc[i][0]);
                    acc[i][1] = ffma2(w, x0.y, acc[i][1]);
                    acc[i][2] = ffma2(w, x1.x, acc[i][2]);
                    acc[i][3] = ffma2(w, x1.y, acc[i][3]);
                }
            }
        }
    }
}

// ---------------------------------------------------------------------------
// Kernel 2: fused side path + attention + FFN. 512 threads, 1 CTA/SM.
// ---------------------------------------------------------------------------
static constexpr int K2_XS = 0;
static constexpr int K2_HS = 128 * PXF;                 // 16384
static constexpr int K2_KS = K2_HS + 128 * PXF;         // 32768
static constexpr int K2_VS = K2_KS + 128 * PXK;         // 41472
static constexpr int K2_WT = K2_VS + 128 * PXK;         // 50176 (16B aligned)
static constexpr int K2_RS = K2_WT + 2 * (2 * WPAR);    // + 4112 floats
static constexpr int K2_SMEM_BYTES = (K2_RS + 128) * 4; // 217,664 B

__global__ void __launch_bounds__(512, 1) main_kernel(
    const float* __restrict__ side,      const float* __restrict__ basis,
    const float* __restrict__ qn_gamma,
    const float* __restrict__ qmlp_in_w, const float* __restrict__ qmlp_in_b,
    const float* __restrict__ qmlp_out_w,const float* __restrict__ qmlp_out_b,
    const float* __restrict__ q_w,       const float* __restrict__ q_b,
    const float* __restrict__ o_w,       const float* __restrict__ o_b,
    const float* __restrict__ ffn_gamma,
    const float* __restrict__ ffn_in_w,  const float* __restrict__ ffn_in_b,
    const float* __restrict__ ffn_out_w, const float* __restrict__ ffn_out_b,
    const float* __restrict__ score_scale, const float* __restrict__ prior_scale,
    const float* __restrict__ query_skip_scale,
    float* __restrict__ out)
{
    extern __shared__ float sm[];
    float* Xs  = sm + K2_XS;
    float* Hs  = sm + K2_HS;
    float* Ks  = sm + K2_KS;
    float* Vs  = sm + K2_VS;
    ull*   Wts = reinterpret_cast<ull*>(sm + K2_WT);
    float* rstd = sm + K2_RS;

    const int tid = threadIdx.x;
    const int fc = blockIdx.x;      // 0..3
    const int t  = blockIdx.y;
    const int b  = blockIdx.z;
    const int f0 = fc * FC;
    const int tx = tid & 15, ty = tid >> 4;   // ty 0..31
    const int frame = b * T + t;

    // ---- load k/v frame into smem (pitch 64 -> 68) ----
    {
        const float* ksrc = g_kbuf + (size_t)frame * (C * K);
        const float* vsrc = g_vbuf + (size_t)frame * (C * K);
        #pragma unroll
        for (int idx = tid; idx < 128 * 16; idx += 512) {
            int r = idx >> 4, q = idx & 15;
            float4 kv = *reinterpret_cast<const float4*>(ksrc + r * K + q * 4);
            float4 vv = *reinterpret_cast<const float4*>(vsrc + r * K + q * 4);
            *reinterpret_cast<float4*>(Ks + r * PXK + q * 4) = kv;
            *reinterpret_cast<float4*>(Vs + r * PXK + q * 4) = vv;
        }
    }
    // ---- load side chunk [128][128] ----
    const float* sbase = side + ((size_t)b * C * T + t) * F + f0;
    #pragma unroll
    for (int idx = tid; idx < 128 * 32; idx += 512) {
        int r = idx >> 5, q = idx & 31;
        float4 v = *reinterpret_cast<const float4*>(sbase + (size_t)r * (T * F) + q * 4);
        *reinterpret_cast<float4*>(Xs + r * PXF + q * 4) = v;
    }
    __syncthreads();
    // ---- rmsnorm (axis C) ----
    if (tid < 128) {
        float s0 = 0, s1 = 0, s2 = 0, s3 = 0;
        for (int c = 0; c < 128; c += 4) {
            float a = Xs[c * PXF + tid], bb = Xs[(c + 1) * PXF + tid];
            float cc = Xs[(c + 2) * PXF + tid], dd = Xs[(c + 3) * PXF + tid];
            s0 += a * a; s1 += bb * bb; s2 += cc * cc; s3 += dd * dd;
        }
        rstd[tid] = rsqrtf((s0 + s1 + s2 + s3) * (1.0f / 128.0f) + 1e-6f);
    }
    __syncthreads();
    #pragma unroll
    for (int idx = tid; idx < 128 * 32; idx += 512) {
        int r = idx >> 5, q = idx & 31;
        float g = qn_gamma[r];
        float* d = Xs + r * PXF + q * 4;
        d[0] *= rstd[q * 4 + 0] * g; d[1] *= rstd[q * 4 + 1] * g;
        d[2] *= rstd[q * 4 + 2] * g; d[3] *= rstd[q * 4 + 3] * g;
    }

    // epilogue helper ---------------------------------------------------------
    auto acc_to_f4 = [](ull a0, ull a1, float bias) {
        float4 v;
        unpack2(a0, v.x, v.y); unpack2(a1, v.z, v.w);
        v.x += bias; v.y += bias; v.z += bias; v.w += bias;
        return v;
    };

    // ---- GEMM1: qmlp_in (gated, two 128-row passes) -> m in Hs ----
    {   // pass 1: gate rows -> silu(g) into Hs
        ull acc[4][4] = {};
        gemm512(qmlp_in_w + 128 * 128, Xs, Wts, acc, tid);
        #pragma unroll
        for (int i = 0; i < 4; ++i) {
            int r = ty + 32 * i;
            float bg = qmlp_in_b[r + 128];
            float4 va = acc_to_f4(acc[i][0], acc[i][1], bg);
            float4 vb = acc_to_f4(acc[i][2], acc[i][3], bg);
            va.x = silu_f(va.x); va.y = silu_f(va.y); va.z = silu_f(va.z); va.w = silu_f(va.w);
            vb.x = silu_f(vb.x); vb.y = silu_f(vb.y); vb.z = silu_f(vb.z); vb.w = silu_f(vb.w);
            *reinterpret_cast<float4*>(Hs + r * PXF + 4 * tx)      = va;
            *reinterpret_cast<float4*>(Hs + r * PXF + 4 * tx + 64) = vb;
        }
    }
    {   // pass 2: a rows; m = (a+b) * silu(g)
        ull acc[4][4] = {};
        gemm512(qmlp_in_w, Xs, Wts, acc, tid);
        #pragma unroll
        for (int i = 0; i < 4; ++i) {
            int r = ty + 32 * i;
            float ba = qmlp_in_b[r];
            float4 va = acc_to_f4(acc[i][0], acc[i][1], ba);
            float4 vb = acc_to_f4(acc[i][2], acc[i][3], ba);
            float4 g0 = *reinterpret_cast<float4*>(Hs + r * PXF + 4 * tx);
            float4 g1 = *reinterpret_cast<float4*>(Hs + r * PXF + 4 * tx + 64);
            g0.x *= va.x; g0.y *= va.y; g0.z *= va.z; g0.w *= va.w;
            g1.x *= vb.x; g1.y *= vb.y; g1.z *= vb.z; g1.w *= vb.w;
            *reinterpret_cast<float4*>(Hs + r * PXF + 4 * tx)      = g0;
            *reinterpret_cast<float4*>(Hs + r * PXF + 4 * tx + 64) = g1;
        }
    }
    // ---- GEMM2: qmlp_out -> query_h in Xs ----
    {
        ull acc[4][4] = {};
        gemm512(qmlp_out_w, Hs, Wts, acc, tid);
        #pragma unroll
        for (int i = 0; i < 4; ++i) {
            int r = ty + 32 * i;
            float bias = qmlp_out_b[r];
            *reinterpret_cast<float4*>(Xs + r * PXF + 4 * tx)      = acc_to_f4(acc[i][0], acc[i][1], bias);
            *reinterpret_cast<float4*>(Xs + r * PXF + 4 * tx + 64) = acc_to_f4(acc[i][2], acc[i][3], bias);
        }
    }
    // ---- GEMM3: q projection -> Hs ----
    {
        ull acc[4][4] = {};
        gemm512(q_w, Xs, Wts, acc, tid);
        #pragma unroll
        for (int i = 0; i < 4; ++i) {
            int r = ty + 32 * i;
            float bias = q_b[r];
            *reinterpret_cast<float4*>(Hs + r * PXF + 4 * tx)      = acc_to_f4(acc[i][0], acc[i][1], bias);
            *reinterpret_cast<float4*>(Hs + r * PXF + 4 * tx + 64) = acc_to_f4(acc[i][2], acc[i][3], bias);
        }
    }
    __syncthreads();   // q fully in Hs before scores

    // ---- scores [f][k] + softmax over k. 512 threads: 2 f x 8 k each ----
    const int kg = tid & 7, fg = tid >> 3;    // fg 0..63
    float wgt[2][8];
    {
        ull sacc[2][4] = {};
        #pragma unroll 4
        for (int c = 0; c < 128; ++c) {
            float2 qv = *reinterpret_cast<const float2*>(Hs + c * PXF + 2 * fg);
            const ulonglong2* kr = reinterpret_cast<const ulonglong2*>(Ks + c * PXK + kg * 8);
            ulonglong2 k0 = kr[0], k1 = kr[1];
            ull qp0 = pack2(qv.x, qv.x), qp1 = pack2(qv.y, qv.y);
            sacc[0][0] = ffma2(qp0, k0.x, sacc[0][0]);
            sacc[0][1] = ffma2(qp0, k0.y, sacc[0][1]);
            sacc[0][2] = ffma2(qp0, k1.x, sacc[0][2]);
            sacc[0][3] = ffma2(qp0, k1.y, sacc[0][3]);
            sacc[1][0] = ffma2(qp1, k0.x, sacc[1][0]);
            sacc[1][1] = ffma2(qp1, k0.y, sacc[1][1]);
            sacc[1][2] = ffma2(qp1, k1.x, sacc[1][2]);
            sacc[1][3] = ffma2(qp1, k1.y, sacc[1][3]);
        }
        const float ssc = *score_scale, psc = *prior_scale;
        #pragma unroll
        for (int i = 0; i < 2; ++i) {
            float s[8];
            #pragma unroll
            for (int jp = 0; jp < 4; ++jp) unpack2(sacc[i][jp], s[2 * jp], s[2 * jp + 1]);
            int fglob = f0 + 2 * fg + i;
            #pragma unroll
            for (int j = 0; j < 8; ++j)
                s[j] = s[j] * ssc + basis[(kg * 8 + j) * F + fglob] * psc;
            float m = s[0];
            #pragma unroll
            for (int j = 1; j < 8; ++j) m = fmaxf(m, s[j]);
            #pragma unroll
            for (int d = 1; d < 8; d <<= 1) m = fmaxf(m, __shfl_xor_sync(0xffffffffu, m, d));
            float sum = 0;
            #pragma unroll
            for (int j = 0; j < 8; ++j) { float e = __expf(s[j] - m); wgt[i][j] = e; sum += e; }
            #pragma unroll
            for (int d = 1; d < 8; d <<= 1) sum += __shfl_xor_sync(0xffffffffu, sum, d);
            float inv = __frcp_rn(sum);
            #pragma unroll
            for (int j = 0; j < 8; ++j) wgt[i][j] *= inv;
        }
    }
    __syncthreads();   // all reads of Ks + q reads of Hs done
    {   // store weights transposed into the dead Ks region: Ws[k][f], pitch PXF
        float* Ws = Ks;
        #pragma unroll
        for (int j = 0; j < 8; ++j)
            *reinterpret_cast<float2*>(Ws + (kg * 8 + j) * PXF + 2 * fg) =
                make_float2(wgt[0][j], wgt[1][j]);
    }
    __syncthreads();
    // ---- attended[c][f] = sum_k Ws[k][f] * Vs[c][k] -> Hs ----
    {
        ull acc[4][4] = {};
        const float* Ws = Ks;
        #pragma unroll 4
        for (int kk = 0; kk < 64; ++kk) {
            const float* wsrow = Ws + kk * PXF + 4 * tx;
            ulonglong2 x0 = *reinterpret_cast<const ulonglong2*>(wsrow);
            ulonglong2 x1 = *reinterpret_cast<const ulonglong2*>(wsrow + 64);
            #pragma unroll
            for (int i = 0; i < 4; ++i) {
                float v = Vs[(ty + 32 * i) * PXK + kk];
                ull vp = pack2(v, v);
                acc[i][0] = ffma2(vp, x0.x, acc[i][0]);
                acc[i][1] = ffma2(vp, x0.y, acc[i][1]);
                acc[i][2] = ffma2(vp, x1.x, acc[i][2]);
                acc[i][3] = ffma2(vp, x1.y, acc[i][3]);
            }
        }
        #pragma unroll
        for (int i = 0; i < 4; ++i) {
            int r = ty + 32 * i;
            *reinterpret_cast<float4*>(Hs + r * PXF + 4 * tx)      = acc_to_f4(acc[i][0], acc[i][1], 0.0f);
            *reinterpret_cast<float4*>(Hs + r * PXF + 4 * tx + 64) = acc_to_f4(acc[i][2], acc[i][3], 0.0f);
        }
    }
    // ---- GEMM4: hidden = o_w @ attended + o_b + qss*query_h -> Xs (in place) ----
    {
        ull acc[4][4] = {};
        gemm512(o_w, Hs, Wts, acc, tid);
        const float qs = *query_skip_scale;
        #pragma unroll
        for (int i = 0; i < 4; ++i) {
            int r = ty + 32 * i;
            float bias = o_b[r];
            float4 va = acc_to_f4(acc[i][0], acc[i][1], bias);
            float4 vb = acc_to_f4(acc[i][2], acc[i][3], bias);
            float4 qa = *reinterpret_cast<float4*>(Xs + r * PXF + 4 * tx);
            float4 qb = *reinterpret_cast<float4*>(Xs + r * PXF + 4 * tx + 64);
            va.x += qs * qa.x; va.y += qs * qa.y; va.z += qs * qa.z; va.w += qs * qa.w;
            vb.x += qs * qb.x; vb.y += qs * qb.y; vb.z += qs * qb.z; vb.w += qs * qb.w;
            *reinterpret_cast<float4*>(Xs + r * PXF + 4 * tx)      = va;
            *reinterpret_cast<float4*>(Xs + r * PXF + 4 * tx + 64) = vb;
        }
    }
    __syncthreads();
    // ---- FFN rmsnorm: Hs = rmsnorm(Xs)*ffn_gamma ----
    if (tid < 128) {
        float s0 = 0, s1 = 0, s2 = 0, s3 = 0;
        for (int c = 0; c < 128; c += 4) {
            float a = Xs[c * PXF + tid], bb = Xs[(c + 1) * PXF + tid];
            float cc = Xs[(c + 2) * PXF + tid], dd = Xs[(c + 3) * PXF + tid];
            s0 += a * a; s1 += bb * bb; s2 += cc * cc; s3 += dd * dd;
        }
        rstd[tid] = rsqrtf((s0 + s1 + s2 + s3) * (1.0f / 128.0f) + 1e-6f);
    }
    __syncthreads();
    #pragma unroll
    for (int idx = tid; idx < 128 * 32; idx += 512) {
        int r = idx >> 5, q = idx & 31;
        float g = ffn_gamma[r];
        const float* s = Xs + r * PXF + q * 4;
        float* d = Hs + r * PXF + q * 4;
        d[0] = s[0] * rstd[q * 4 + 0] * g; d[1] = s[1] * rstd[q * 4 + 1] * g;
        d[2] = s[2] * rstd[q * 4 + 2] * g; d[3] = s[3] * rstd[q * 4 + 3] * g;
    }
    // ---- GEMM5: ffn_in (gated, two passes), intermediate Gb = dead Ks+Vs ----
    float* Gb = Ks;
    {   // pass 1: gate rows -> silu into Gb
        ull acc[4][4] = {};
        gemm512(ffn_in_w + 128 * 128, Hs, Wts, acc, tid);
        #pragma unroll
        for (int i = 0; i < 4; ++i) {
            int r = ty + 32 * i;
            float bg = ffn_in_b[r + 128];
            float4 va = acc_to_f4(acc[i][0], acc[i][1], bg);
            float4 vb = acc_to_f4(acc[i][2], acc[i][3], bg);
            va.x = silu_f(va.x); va.y = silu_f(va.y); va.z = silu_f(va.z); va.w = silu_f(va.w);
            vb.x = silu_f(vb.x); vb.y = silu_f(vb.y); vb.z = silu_f(vb.z); vb.w = silu_f(vb.w);
            *reinterpret_cast<float4*>(Gb + r * PXF + 4 * tx)      = va;
            *reinterpret_cast<float4*>(Gb + r * PXF + 4 * tx + 64) = vb;
        }
    }
    {   // pass 2: a rows; m2 = (a+b)*silu(g) into Gb
        ull acc[4][4] = {};
        gemm512(ffn_in_w, Hs, Wts, acc, tid);
        #pragma unroll
        for (int i = 0; i < 4; ++i) {
            int r = ty + 32 * i;
            float ba = ffn_in_b[r];
            float4 va = acc_to_f4(acc[i][0], acc[i][1], ba);
            float4 vb = acc_to_f4(acc[i][2], acc[i][3], ba);
            float4 g0 = *reinterpret_cast<float4*>(Gb + r * PXF + 4 * tx);
            float4 g1 = *reinterpret_cast<float4*>(Gb + r * PXF + 4 * tx + 64);
            g0.x *= va.x; g0.y *= va.y; g0.z *= va.z; g0.w *= va.w;
            g1.x *= vb.x; g1.y *= vb.y; g1.z *= vb.z; g1.w *= vb.w;
            *reinterpret_cast<float4*>(Gb + r * PXF + 4 * tx)      = g0;
            *reinterpret_cast<float4*>(Gb + r * PXF + 4 * tx + 64) = g1;
        }
    }
    // ---- GEMM6: out = ffn_out @ m2 + ffn_out_b + hidden -> global ----
    {
        ull acc[4][4] = {};
        gemm512(ffn_out_w, Gb, Wts, acc, tid);
        float* obase = out + ((size_t)b * C * T + t) * F + f0;
        #pragma unroll
        for (int i = 0; i < 4; ++i) {
            int r = ty + 32 * i;
            float bias = ffn_out_b[r];
            float4 va = acc_to_f4(acc[i][0], acc[i][1], bias);
            float4 vb = acc_to_f4(acc[i][2], acc[i][3], bias);
            float4 ha = *reinterpret_cast<float4*>(Xs + r * PXF + 4 * tx);
            float4 hb = *reinterpret_cast<float4*>(Xs + r * PXF + 4 * tx + 64);
            va.x += ha.x; va.y += ha.y; va.z += ha.z; va.w += ha.w;
            vb.x += hb.x; vb.y += hb.y; vb.z += hb.z; vb.w += hb.w;
            *reinterpret_cast<float4*>(obase + (size_t)r * (T * F) + 4 * tx)      = va;
            *reinterpret_cast<float4*>(obase + (size_t)r * (T * F) + 4 * tx + 64) = vb;
        }
    }
}

// ---------------------------------------------------------------------------
extern "C" void kernel_launch(void* const* d_in, const int* in_sizes, int n_in,
                              void* d_out, int out_size)
{
    const float* latent      = (const float*)d_in[0];
    const float* side        = (const float*)d_in[1];
    const float* basis       = (const float*)d_in[2];
    const float* lp_gamma    = (const float*)d_in[3];
    const float* lp_w        = (const float*)d_in[4];
    const float* lp_b        = (const float*)d_in[5];
    const float* qn_gamma    = (const float*)d_in[6];
    const float* qmlp_in_w   = (const float*)d_in[7];
    const float* qmlp_in_b   = (const float*)d_in[8];
    const float* qmlp_out_w  = (const float*)d_in[9];
    const float* qmlp_out_b  = (const float*)d_in[10];
    const float* q_w         = (const float*)d_in[11];
    const float* q_b         = (const float*)d_in[12];
    const float* k_w         = (const float*)d_in[13];
    const float* k_b         = (const float*)d_in[14];
    const float* v_w         = (const float*)d_in[15];
    const float* v_b         = (const float*)d_in[16];
    const float* o_w         = (const float*)d_in[17];
    const float* o_b         = (const float*)d_in[18];
    const float* ffn_gamma   = (const float*)d_in[19];
    const float* ffn_in_w    = (const float*)d_in[20];
    const float* ffn_in_b    = (const float*)d_in[21];
    const float* ffn_out_w   = (const float*)d_in[22];
    const float* ffn_out_b   = (const float*)d_in[23];
    const float* score_scale = (const float*)d_in[24];
    const float* prior_scale = (const float*)d_in[25];
    const float* qss         = (const float*)d_in[26];
    float* out = (float*)d_out;

    cudaFuncSetAttribute(latent_kernel, cudaFuncAttributeMaxDynamicSharedMemorySize, K1_SMEM_BYTES);
    cudaFuncSetAttribute(main_kernel,   cudaFuncAttributeMaxDynamicSharedMemorySize, K2_SMEM_BYTES);

    latent_kernel<<<B * T, 256, K1_SMEM_BYTES>>>(
        latent, lp_gamma, lp_w, lp_b, k_w, k_b, v_w, v_b);

    main_kernel<<<dim3(F / FC, T, B), 512, K2_SMEM_BYTES>>>(
        side, basis, qn_gamma,
        qmlp_in_w, qmlp_in_b, qmlp_out_w, qmlp_out_b,
        q_w, q_b, o_w, o_b,
        ffn_gamma, ffn_in_w, ffn_in_b, ffn_out_w, ffn_out_b,
        score_scale, prior_scale, qss, out);
}